// round 11
// baseline (speedup 1.0000x reference)
#include <cuda_runtime.h>
#include <cuda_fp16.h>
#include <cstdint>

// Problem constants
#define M_SUB   8
#define N_E     1024
#define E_DIM   64
#define BS_     16
#define CC_     512
#define HW_     1024
#define NPOS    16384            // BS_*HW_

// Output layout (float32)
#define OFF_ZVQ  0
#define OFF_LOSS 8388608
#define OFF_IDX  8388609
#define OFF_BIN  8519681

#define CAP   32        // candidate cap per row
#define EPSF  2e-3f     // collect threshold (>= 4x worst-case fp16 error bound)

#define CHUNK_BYTES 8448   // 16 rows x 528B (512B data + 16B pad per row)

// Scratch (device globals; no allocation allowed)
__device__ float  g_esq[M_SUB * N_E];
// fp16 codebooks packed in m16n8k16 B-fragment order:
// [m][ch(16)] chunk of 16 rows (kp = ks*4+lx) x 64 uint2 (pos = gg*8+nt), row stride 528B
__device__ __align__(16) unsigned char g_cbh[M_SUB * 16 * CHUNK_BYTES];
__device__ double g_part[1024];

// ---------------- helpers ------------------------------------------------------
__device__ __forceinline__ unsigned h2u(__half2 h) {
    return *reinterpret_cast<unsigned*>(&h);
}
__device__ __forceinline__ void mma_f16(float* d, const unsigned* a,
                                        unsigned b0, unsigned b1) {
    asm volatile("mma.sync.aligned.m16n8k16.row.col.f32.f16.f16.f32 "
                 "{%0,%1,%2,%3}, {%4,%5,%6,%7}, {%8,%9}, {%0,%1,%2,%3};"
                 : "+f"(d[0]), "+f"(d[1]), "+f"(d[2]), "+f"(d[3])
                 : "r"(a[0]), "r"(a[1]), "r"(a[2]), "r"(a[3]), "r"(b0), "r"(b1));
}
__device__ __forceinline__ void cp_async16(unsigned dst, const void* src) {
    asm volatile("cp.async.cg.shared.global [%0], [%1], 16;" :: "r"(dst), "l"(src));
}
#define CP_COMMIT() asm volatile("cp.async.commit_group;")
#define CP_WAIT0()  asm volatile("cp.async.wait_group 0;" ::: "memory")

// ---------------- K0: zero bins -------------------------------------------------
__global__ void pq_init_kernel(float* __restrict__ outBins) {
    int t = threadIdx.x;
    if (t < N_E) outBins[t] = 0.0f;
}

// ---------------- K_esq: per-code squared norms (mul then sequential add) -------
__global__ void pq_esq_kernel(const float* __restrict__ cbk) {
    int t = blockIdx.x * blockDim.x + threadIdx.x;
    if (t >= M_SUB * N_E) return;
    const float* p = cbk + (size_t)t * E_DIM;
    float s = 0.0f;
    #pragma unroll
    for (int d = 0; d < E_DIM; d++) {
        float v = p[d];
        s = __fadd_rn(s, __fmul_rn(v, v));
    }
    g_esq[t] = s;
}

// ---------------- K_tr: pack codebooks into fp16 mma-fragment order -------------
// grid = 128 blocks (m x ch), 256 threads
__global__ void pq_tr_kernel(const float* __restrict__ cbk) {
    __shared__ float st[64 * 65];             // [j(code local)][k]
    int m  = blockIdx.x >> 4;
    int ch = blockIdx.x & 15;
    int tid = threadIdx.x;
    const float* src = cbk + ((size_t)(m * N_E) + ch * 64) * E_DIM;
    #pragma unroll
    for (int it = 0; it < 4; it++) {
        int i = tid + it * 256;               // 0..1023 float4 slots
        int j = i >> 4, k4 = (i & 15) * 4;
        float4 v = *(const float4*)(src + (size_t)j * E_DIM + k4);
        float* dp = st + j * 65 + k4;
        dp[0] = v.x; dp[1] = v.y; dp[2] = v.z; dp[3] = v.w;
    }
    __syncthreads();
    uint2* dst = (uint2*)(g_cbh + (size_t)(m * 16 + ch) * CHUNK_BYTES);
    #pragma unroll
    for (int it = 0; it < 4; it++) {
        int idx = tid + it * 256;             // 0..1023
        int kp = idx >> 6, pos = idx & 63;
        int gg = pos >> 3, nt = pos & 7;
        int j = nt * 8 + gg;                  // code local index
        int k0 = (kp >> 2) * 16 + (kp & 3) * 2;
        const float* r = st + j * 65;
        uint2 v;
        v.x = h2u(__floats2half2_rn(r[k0],     r[k0 + 1]));
        v.y = h2u(__floats2half2_rn(r[k0 + 8], r[k0 + 9]));
        dst[kp * 66 + pos] = v;               // row stride 528B = 66 uint2
    }
}

// ---------------- K1: fp16 MMA scoring + exact rescore + fused epilogue ---------
// Block 256 threads (8 warps). Tile: 128 rows x 1024 codes. grid = (128, 8).
// smem carve (floats):
#define S_ZT    0            // z tile [128][65]            (8320)
#define S_SPB   8320         // B dbl-buf 2 x 2112          (4224)
#define S_CAND  12544        // candidates [128][CAP] int   (4096)
#define S_ESQ   16640        // esq                         (1024)
#define S_ZSQ   17664        // zsq                         (128)
#define S_CNT   17792        // counters int                (128)
#define S_WIN   17920        // winners int                 (128)
#define S_RBD   18048        // rescore partial d           (256)
#define S_RBI   18304        // rescore partial idx int     (256)
#define S_TOT   18560        // 74240 bytes
#define S_SQ    8320         // gather overlay (8320 = 4224+4096)

__global__ void __launch_bounds__(256, 3)
pq_dist_kernel(const float* __restrict__ z,
               const float* __restrict__ cbk,
               float* __restrict__ outZvq,
               float* __restrict__ outIdx,
               float* __restrict__ outBins)
{
    extern __shared__ float sm[];
    float*    szt  = sm + S_ZT;
    float*    spb  = sm + S_SPB;
    int*      scand= (int*)(sm + S_CAND);
    float*    sesq = sm + S_ESQ;
    float*    szsq = sm + S_ZSQ;
    int*      scnt = (int*)(sm + S_CNT);
    int*      swin = (int*)(sm + S_WIN);
    float*    rbd  = sm + S_RBD;
    int*      rbi  = (int*)(sm + S_RBI);
    __shared__ double swarp[8];

    const int m  = blockIdx.y;
    const int n0 = blockIdx.x * 128;
    const int b  = n0 >> 10;
    const int p0 = n0 & 1023;
    const int tid  = threadIdx.x;
    const int wid  = tid >> 5;
    const int lane = tid & 31;
    const int gg   = lane >> 2;      // group id 0..7
    const int lx   = lane & 3;       // thread-in-group
    const int row0 = wid * 16 + gg;
    const float INFF = __int_as_float(0x7f800000);

    // ---- load z tile [pos][d] (transpose from gmem [d][pos]) ----
    const float* zbase = z + ((size_t)(b * CC_ + m * E_DIM) * HW_) + p0;
    #pragma unroll
    for (int it = 0; it < 8; it++) {
        int i = tid + it * 256;
        int d = i >> 5, j4 = (i & 31) * 4;
        float4 v = *(const float4*)(zbase + (size_t)d * HW_ + j4);
        szt[(j4 + 0) * 65 + d] = v.x;
        szt[(j4 + 1) * 65 + d] = v.y;
        szt[(j4 + 2) * 65 + d] = v.z;
        szt[(j4 + 3) * 65 + d] = v.w;
    }
    #pragma unroll
    for (int it = 0; it < 4; it++)
        sesq[tid + it * 256] = g_esq[m * N_E + tid + it * 256];
    if (tid < 128) scnt[tid] = 0;

    // ---- prologue: async-load chunk 0 into buffer 0 ----
    unsigned spb_u32 = (unsigned)__cvta_generic_to_shared(spb);
    const unsigned char* gchunk = g_cbh + (size_t)(m * 16) * CHUNK_BYTES;
    #pragma unroll
    for (int it = 0; it < 2; it++) {
        int i = tid + it * 256;
        int off = (i >> 5) * 528 + (i & 31) * 16;
        cp_async16(spb_u32 + off, gchunk + off);
    }
    CP_COMMIT(); CP_WAIT0();
    __syncthreads();

    // ---- per-row ||z||^2 (sequential chain, matches reference) ----
    if (tid < 128) {
        float s = 0.0f;
        const float* zr = szt + tid * 65;
        #pragma unroll
        for (int k = 0; k < E_DIM; k++)
            s = __fadd_rn(s, __fmul_rn(zr[k], zr[k]));
        szsq[tid] = s;
    }

    // ---- A fragments fp16 (held in regs): rows row0/row0+8, k=64 ----
    unsigned afr[4][4];
    {
        const float* zr0 = szt + row0 * 65;
        const float* zr1 = szt + (row0 + 8) * 65;
        #pragma unroll
        for (int ks = 0; ks < 4; ks++) {
            int k0 = 16 * ks + 2 * lx;
            afr[ks][0] = h2u(__floats2half2_rn(zr0[k0],     zr0[k0 + 1]));
            afr[ks][1] = h2u(__floats2half2_rn(zr1[k0],     zr1[k0 + 1]));
            afr[ks][2] = h2u(__floats2half2_rn(zr0[k0 + 8], zr0[k0 + 9]));
            afr[ks][3] = h2u(__floats2half2_rn(zr1[k0 + 8], zr1[k0 + 9]));
        }
    }

    #define PUSH(rw, cc) { int p_ = atomicAdd(scnt + (rw), 1); \
                           if (p_ < CAP) scand[(rw) * CAP + p_] = (cc); }

    // ---- 16 chunks of 64 codes ----
    float rm0 = INFF, rm1 = INFF;     // row running mins (shared across 4 lanes)
    float thr0 = INFF, thr1 = INFF;   // lagged thresholds
    for (int ch = 0; ch < 16; ch++) {
        const float* cur = spb + (ch & 1) * 2112;
        if (ch < 15) {
            unsigned nxt_u32 = spb_u32 + ((ch + 1) & 1) * CHUNK_BYTES;
            const unsigned char* gsrc = gchunk + (ch + 1) * CHUNK_BYTES;
            #pragma unroll
            for (int it = 0; it < 2; it++) {
                int i = tid + it * 256;
                int off = (i >> 5) * 528 + (i & 31) * 16;
                cp_async16(nxt_u32 + off, gsrc + off);
            }
            CP_COMMIT();
        }

        float acc[8][4];
        #pragma unroll
        for (int nt = 0; nt < 8; nt++)
            #pragma unroll
            for (int q = 0; q < 4; q++) acc[nt][q] = 0.0f;

        const float* bp = cur + lx * 132 + gg * 16;   // row kp=ks*4+lx, col gg
        #pragma unroll
        for (int ks = 0; ks < 4; ks++) {
            const uint4* b4 = (const uint4*)(bp + ks * 528);
            #pragma unroll
            for (int q = 0; q < 4; q++) {
                uint4 bb = b4[q];
                mma_f16(acc[2 * q],     afr[ks], bb.x, bb.y);
                mma_f16(acc[2 * q + 1], afr[ks], bb.z, bb.w);
            }
        }

        // scores: esq[c] - 2*dot; codes for acc[nt] = ch*64 + nt*8 + 2lx, +1
        const int cb0 = ch * 64 + 2 * lx;
        float m0 = INFF, m1 = INFF;
        if (ch == 0) {
            // two-pass for first chunk (no valid lagged threshold yet)
            #pragma unroll
            for (int nt = 0; nt < 8; nt++) {
                float2 e = *(const float2*)(sesq + cb0 + nt * 8);
                float s0 = __fmaf_rn(acc[nt][0], -2.0f, e.x);
                float s1 = __fmaf_rn(acc[nt][1], -2.0f, e.y);
                float s2 = __fmaf_rn(acc[nt][2], -2.0f, e.x);
                float s3 = __fmaf_rn(acc[nt][3], -2.0f, e.y);
                m0 = fminf(m0, fminf(s0, s1));
                m1 = fminf(m1, fminf(s2, s3));
            }
            #pragma unroll
            for (int off = 1; off <= 2; off <<= 1) {
                m0 = fminf(m0, __shfl_xor_sync(0xffffffffu, m0, off));
                m1 = fminf(m1, __shfl_xor_sync(0xffffffffu, m1, off));
            }
            rm0 = m0; thr0 = rm0 + EPSF;
            rm1 = m1; thr1 = rm1 + EPSF;
            #pragma unroll
            for (int nt = 0; nt < 8; nt++) {
                int c = cb0 + nt * 8;
                float2 e = *(const float2*)(sesq + c);
                float s0 = __fmaf_rn(acc[nt][0], -2.0f, e.x);
                float s1 = __fmaf_rn(acc[nt][1], -2.0f, e.y);
                float s2 = __fmaf_rn(acc[nt][2], -2.0f, e.x);
                float s3 = __fmaf_rn(acc[nt][3], -2.0f, e.y);
                if (s0 <= thr0) PUSH(row0, c);
                if (s1 <= thr0) PUSH(row0, c + 1);
                if (s2 <= thr1) PUSH(row0 + 8, c);
                if (s3 <= thr1) PUSH(row0 + 8, c + 1);
            }
        } else {
            // single pass, lagged threshold (safe: 2e < EPSF)
            #pragma unroll
            for (int nt = 0; nt < 8; nt++) {
                int c = cb0 + nt * 8;
                float2 e = *(const float2*)(sesq + c);
                float s0 = __fmaf_rn(acc[nt][0], -2.0f, e.x);
                float s1 = __fmaf_rn(acc[nt][1], -2.0f, e.y);
                float s2 = __fmaf_rn(acc[nt][2], -2.0f, e.x);
                float s3 = __fmaf_rn(acc[nt][3], -2.0f, e.y);
                if (s0 <= thr0) PUSH(row0, c);
                if (s1 <= thr0) PUSH(row0, c + 1);
                if (s2 <= thr1) PUSH(row0 + 8, c);
                if (s3 <= thr1) PUSH(row0 + 8, c + 1);
                m0 = fminf(m0, fminf(s0, s1));
                m1 = fminf(m1, fminf(s2, s3));
            }
            #pragma unroll
            for (int off = 1; off <= 2; off <<= 1) {
                m0 = fminf(m0, __shfl_xor_sync(0xffffffffu, m0, off));
                m1 = fminf(m1, __shfl_xor_sync(0xffffffffu, m1, off));
            }
            rm0 = fminf(rm0, m0); thr0 = rm0 + EPSF;
            rm1 = fminf(rm1, m1); thr1 = rm1 + EPSF;
        }

        if (ch < 15) CP_WAIT0();
        __syncthreads();
    }

    // ---- exact rescore (reference-identical fp32 chains); 2 threads per row ----
    {
        int row = (tid < 128) ? tid : tid - 128;
        int start = (tid < 128) ? 0 : 1;
        int cnt = scnt[row];
        const float* zr = szt + row * 65;
        float zsqv = szsq[row];
        const float* cbm = cbk + (size_t)m * N_E * E_DIM;
        float bd = INFF; int bi = 0x7fffffff;

        auto exact_d = [&](int c) -> float {
            const float* cr = cbm + (size_t)c * E_DIM;
            float s = 0.0f;
            #pragma unroll
            for (int g4 = 0; g4 < 4; g4++) {
                float4 c0 = *(const float4*)(cr + g4 * 16);
                float4 c1 = *(const float4*)(cr + g4 * 16 + 4);
                float4 c2 = *(const float4*)(cr + g4 * 16 + 8);
                float4 c3 = *(const float4*)(cr + g4 * 16 + 12);
                const float* zp = zr + g4 * 16;
                s = __fmaf_rn(zp[0],  c0.x, s); s = __fmaf_rn(zp[1],  c0.y, s);
                s = __fmaf_rn(zp[2],  c0.z, s); s = __fmaf_rn(zp[3],  c0.w, s);
                s = __fmaf_rn(zp[4],  c1.x, s); s = __fmaf_rn(zp[5],  c1.y, s);
                s = __fmaf_rn(zp[6],  c1.z, s); s = __fmaf_rn(zp[7],  c1.w, s);
                s = __fmaf_rn(zp[8],  c2.x, s); s = __fmaf_rn(zp[9],  c2.y, s);
                s = __fmaf_rn(zp[10], c2.z, s); s = __fmaf_rn(zp[11], c2.w, s);
                s = __fmaf_rn(zp[12], c3.x, s); s = __fmaf_rn(zp[13], c3.y, s);
                s = __fmaf_rn(zp[14], c3.z, s); s = __fmaf_rn(zp[15], c3.w, s);
            }
            return __fsub_rn(__fadd_rn(zsqv, sesq[c]), __fmul_rn(2.0f, s));
        };

        if (cnt <= CAP) {
            for (int i = start; i < cnt; i += 2) {
                int c = scand[row * CAP + i];
                float d = exact_d(c);
                if (d < bd || (d == bd && c < bi)) { bd = d; bi = c; }
            }
        } else {  // overflow fallback: full exact scan (provably correct, ~never)
            for (int c = start; c < N_E; c += 2) {
                float d = exact_d(c);
                if (d < bd || (d == bd && c < bi)) { bd = d; bi = c; }
            }
        }
        rbd[tid] = bd; rbi[tid] = bi;
    }
    __syncthreads();
    if (tid < 128) {
        float bd = rbd[tid]; int bi = rbi[tid];
        float d2 = rbd[tid + 128]; int i2 = rbi[tid + 128];
        if (d2 < bd || (d2 == bd && i2 < bi)) { bd = d2; bi = i2; }
        swin[tid] = bi;
        outIdx[m * NPOS + n0 + tid] = (float)bi;
        atomicAdd(outBins + bi, 1.0f);   // integer-valued float adds: exact
    }
    __syncthreads();

    // ---- gather winning code rows into sq[row][d], stride 65 (overlay) ----
    float* sq = sm + S_SQ;
    const float* cbm = cbk + (size_t)m * N_E * E_DIM;
    #pragma unroll
    for (int it = 0; it < 8; it++) {
        int i = tid + it * 256;
        int row = i >> 4, d4 = (i & 15) * 4;
        int idx = swin[row];
        float4 v = *(const float4*)(cbm + (size_t)idx * E_DIM + d4);
        float* dp = sq + row * 65 + d4;
        dp[0] = v.x; dp[1] = v.y; dp[2] = v.z; dp[3] = v.w;
    }
    __syncthreads();

    // ---- z_vq = zf + (zq - zf); loss partial in double ----
    double lsum = 0.0;
    float* ob = outZvq + ((size_t)(b * CC_ + m * E_DIM)) * HW_ + p0;
    #pragma unroll
    for (int it = 0; it < 8; it++) {
        int i = tid + it * 256;
        int d = i >> 5, j4 = (i & 31) * 4;
        float o[4];
        #pragma unroll
        for (int q = 0; q < 4; q++) {
            float zf = szt[(j4 + q) * 65 + d];
            float zq = sq[(j4 + q) * 65 + d];
            float df = __fsub_rn(zq, zf);
            o[q] = __fadd_rn(zf, df);
            lsum += (double)df * (double)df;
        }
        *(float4*)(ob + (size_t)d * HW_ + j4) = make_float4(o[0], o[1], o[2], o[3]);
    }

    #pragma unroll
    for (int off = 16; off > 0; off >>= 1)
        lsum += __shfl_down_sync(0xffffffffu, lsum, off);
    if (lane == 0) swarp[wid] = lsum;
    __syncthreads();
    if (wid == 0) {
        double v = (lane < 8) ? swarp[lane] : 0.0;
        #pragma unroll
        for (int off = 4; off > 0; off >>= 1)
            v += __shfl_down_sync(0xffffffffu, v, off);
        if (lane == 0) g_part[m * 128 + blockIdx.x] = v;
    }
}

// ---------------- K3: finalize loss ---------------------------------------------
__global__ void pq_loss_kernel(float* __restrict__ outLoss) {
    __shared__ double sred[256];
    int t = threadIdx.x;
    double s = 0.0;
    for (int i = t; i < 1024; i += 256) s += g_part[i];
    sred[t] = s;
    __syncthreads();
    for (int off = 128; off > 0; off >>= 1) {
        if (t < off) sred[t] += sred[t + off];
        __syncthreads();
    }
    if (t == 0) {
        double loss = 1.25 * sred[0] / (double)((size_t)NPOS * E_DIM);
        outLoss[0] = (float)loss;
    }
}

// ---------------- launch ----------------------------------------------------------
extern "C" void kernel_launch(void* const* d_in, const int* in_sizes, int n_in,
                              void* d_out, int out_size)
{
    const float* z   = (const float*)d_in[0];
    const float* cbk = (const float*)d_in[1];
    if (n_in >= 2 && in_sizes[0] == M_SUB * N_E * E_DIM) {  // swapped-order safety
        z   = (const float*)d_in[1];
        cbk = (const float*)d_in[0];
    }
    float* out = (float*)d_out;
    float* outZvq  = out + OFF_ZVQ;
    float* outLoss = out + OFF_LOSS;
    float* outIdx  = out + OFF_IDX;
    float* outBins = out + OFF_BIN;

    const int dyn_smem = S_TOT * 4;   // 74240 B
    cudaFuncSetAttribute(pq_dist_kernel,
                         cudaFuncAttributeMaxDynamicSharedMemorySize, dyn_smem);

    pq_init_kernel<<<1, 1024>>>(outBins);
    pq_esq_kernel<<<(M_SUB * N_E + 255) / 256, 256>>>(cbk);
    pq_tr_kernel<<<128, 256>>>(cbk);
    dim3 g1(NPOS / 128, M_SUB);
    pq_dist_kernel<<<g1, 256, dyn_smem>>>(z, cbk, outZvq, outIdx, outBins);
    pq_loss_kernel<<<1, 256>>>(outLoss);
}